// round 12
// baseline (speedup 1.0000x reference)
#include <cuda_runtime.h>
#include <math.h>

// Problem constants
#define NN 1024
#define TI 16
#define TJ 32
#define NIB (NN/TI)          // 64 i-blocks
#define NJB (NN/TJ)          // 32 j-blocks
#define FTOT 104             // per-particle reduced features: tp1(32) tp2(32) tp3(32) tp0(8)
#define TPSTR 36             // smem row stride for tp tile (floats), 16B-aligned rows
#define F0STR 12             // smem row stride for tp0 features
#define SCSTR 36             // scratch row stride (col partials), 16B-aligned
#define SPD 64
#define PAIR_THREADS 512

// tail kernel config
#define TB 128               // tail blocks (<=148 SMs -> co-resident, safe grid barrier)
#define TT 256               // tail threads
#define RPB 8                // rows per tail block

typedef unsigned long long u64;

// ---------------- device scratch (static allocation only) ----------------
__device__ float g_rowPart[(size_t)NJB * NN * FTOT];             // 13.6 MB
__device__ float g_colPart[(size_t)NIB * NN * FTOT];             // 27.3 MB
__device__ float g_rowSum[NN * FTOT];
__device__ float g_colSum[NN * FTOT];
__device__ float g_meanPart[2][TB * SPD];                        // double-buffered spin-mean partials
__device__ unsigned g_barCount;
__device__ unsigned g_barGen;

// ---------------- packed fp32x2 helpers ----------------
__device__ __forceinline__ u64 dup2(float v) {
    u64 r; asm("mov.b64 %0, {%1,%1};" : "=l"(r) : "f"(v)); return r;
}
__device__ __forceinline__ u64 pk2(float lo, float hi) {
    u64 r; asm("mov.b64 %0, {%1,%2};" : "=l"(r) : "f"(lo), "f"(hi)); return r;
}
__device__ __forceinline__ void up2(u64 p, float& lo, float& hi) {
    asm("mov.b64 {%0,%1}, %2;" : "=f"(lo), "=f"(hi) : "l"(p));
}
__device__ __forceinline__ u64 fma2_(u64 a, u64 b, u64 c) {
    u64 d; asm("fma.rn.f32x2 %0, %1, %2, %3;" : "=l"(d) : "l"(a), "l"(b), "l"(c)); return d;
}
__device__ __forceinline__ u64 mul2_(u64 a, u64 b) {
    u64 d; asm("mul.rn.f32x2 %0, %1, %2;" : "=l"(d) : "l"(a), "l"(b)); return d;
}
__device__ __forceinline__ u64 add2_(u64 a, u64 b) {
    u64 d; asm("add.rn.f32x2 %0, %1, %2;" : "=l"(d) : "l"(a), "l"(b)); return d;
}

// ---------------- softplus ----------------
__device__ __forceinline__ float softplus_exact(float x) {
    return fmaxf(x, 0.f) + log1pf(expf(-fabsf(x)));
}

struct SPK { u64 a, b, c, d, e, h; };  // packed poly coefficients
__device__ __forceinline__ SPK make_spk() {
    SPK k;
    k.a = dup2(-2.635168e-5f);
    k.b = dup2(3.4722222e-4f);
    k.c = dup2(-5.2083335e-3f);
    k.d = dup2(0.125f);
    k.e = dup2(0.69314718056f);
    k.h = dup2(0.5f);
    return k;
}
// softplus(x) = x/2 + ln(2 cosh(x/2)); even part poly in x^2 (|x|<=1: err < 2e-6)
__device__ __forceinline__ u64 softplus2p(u64 x2, const SPK& k) {
    u64 u = mul2_(x2, x2);
    u64 h = fma2_(u, k.a, k.b);
    h = fma2_(u, h, k.c);
    h = fma2_(u, h, k.d);
    h = fma2_(u, h, k.e);
    u64 r = fma2_(x2, k.h, h);
    float xl, xh; up2(x2, xl, xh);
    if (fabsf(xl) > 1.0f || fabsf(xh) > 1.0f) {
        float rl = fmaxf(xl, 0.f) + log1pf(__expf(-fabsf(xl)));
        float rh = fmaxf(xh, 0.f) + log1pf(__expf(-fabsf(xh)));
        r = pk2(rl, rh);
    }
    return r;
}

// ---------------- pair kernel: fused tp stream (packed fp32x2 GEMM, m=4 blocking) ----------------
// tile: TI=16 i x TJ=32 j = 512 pairs, 512 threads
// GEMM thread (tr,tc): pairs {tr, tr+128, tr+256, tr+384}, packed cols tc*8..tc*8+7
template<int K4, int AS>
__device__ __forceinline__ void gemm_tile2(const float* __restrict__ A,
                                           const float* __restrict__ W,
                                           const float* __restrict__ bias,
                                           int tr, int tc, u64 acc[4][4]) {
    const ulonglong2* bp = (const ulonglong2*)(bias + tc * 8);
    ulonglong2 bb0 = bp[0], bb1 = bp[1];
    #pragma unroll
    for (int m = 0; m < 4; m++) {
        acc[m][0] = bb0.x; acc[m][1] = bb0.y; acc[m][2] = bb1.x; acc[m][3] = bb1.y;
    }
    #pragma unroll
    for (int k4 = 0; k4 < K4; k4++) {
        float4 a[4];
        #pragma unroll
        for (int m = 0; m < 4; m++)
            a[m] = *(const float4*)(A + (tr + 128 * m) * AS + k4 * 4);
        #pragma unroll
        for (int kk = 0; kk < 4; kk++) {
            const ulonglong2* wr = (const ulonglong2*)(W + (k4 * 4 + kk) * 32 + tc * 8);
            ulonglong2 w0 = wr[0], w1 = wr[1];
            #pragma unroll
            for (int m = 0; m < 4; m++) {
                float av = (&a[m].x)[kk];
                u64 av2 = dup2(av);
                acc[m][0] = fma2_(av2, w0.x, acc[m][0]);
                acc[m][1] = fma2_(av2, w0.y, acc[m][1]);
                acc[m][2] = fma2_(av2, w1.x, acc[m][2]);
                acc[m][3] = fma2_(av2, w1.y, acc[m][3]);
            }
        }
    }
}

// row sums from tile (4-way ILP): 512 threads -> 16 rows x 32 feats
__device__ __forceinline__ void rowSums(const float* __restrict__ tp_s, int off,
                                        int i0, int jb, int tid) {
    int il = tid >> 5, n = tid & 31;
    const float* b = tp_s + (il * 32) * TPSTR + n;
    float s0 = 0.f, s1 = 0.f, s2 = 0.f, s3 = 0.f;
    #pragma unroll
    for (int jl = 0; jl < 32; jl += 4) {
        s0 += b[(jl + 0) * TPSTR];
        s1 += b[(jl + 1) * TPSTR];
        s2 += b[(jl + 2) * TPSTR];
        s3 += b[(jl + 3) * TPSTR];
    }
    g_rowPart[((size_t)jb * NN + (i0 + il)) * FTOT + off + n] = (s0 + s1) + (s2 + s3);
}

// col sums stage 2: combine 4 register-presummed partials per (jl, n)
__device__ __forceinline__ void colStage2(const float* __restrict__ scratch, int off,
                                          int j0, int ib, int tid) {
    #pragma unroll
    for (int rep = 0; rep < 2; rep++) {
        int v = tid + rep * 512;
        int jl = v >> 5, n = v & 31;
        float s = (scratch[jl * SCSTR + n] + scratch[(jl + 32) * SCSTR + n])
                + (scratch[(jl + 64) * SCSTR + n] + scratch[(jl + 96) * SCSTR + n]);
        g_colPart[((size_t)ib * NN + (j0 + jl)) * FTOT + off + n] = s;
    }
}

// store thread's tile slice + col partials to the write buffer
__device__ __forceinline__ void storeTile(float* __restrict__ bufW, float* __restrict__ scrW,
                                          const u64 tp[4][4], const u64 colp[4],
                                          int tr, int tc) {
    #pragma unroll
    for (int m = 0; m < 4; m++) {
        ulonglong2* row = (ulonglong2*)(bufW + (tr + 128 * m) * TPSTR + tc * 8);
        row[0] = make_ulonglong2(tp[m][0], tp[m][1]);
        row[1] = make_ulonglong2(tp[m][2], tp[m][3]);
    }
    ulonglong2* sc = (ulonglong2*)(scrW + tr * SCSTR + tc * 8);
    sc[0] = make_ulonglong2(colp[0], colp[1]);
    sc[1] = make_ulonglong2(colp[2], colp[3]);
}

__global__ void __launch_bounds__(PAIR_THREADS, 1)
pairKernel(const float* __restrict__ x,
           const float* __restrict__ tp_w0, const float* __restrict__ tp_b0,
           const float* __restrict__ tp_w,  const float* __restrict__ tp_b) {
    extern __shared__ float smem_f[];
    float* tpA  = smem_f;                 // 512*36 = 18432 floats
    float* tpB  = tpA + 512 * TPSTR;      // 18432 floats
    float* scrA = tpB + 512 * TPSTR;      // 128*36 = 4608 floats
    float* scrB = scrA + 128 * SCSTR;     // 4608 floats
    float* f0_s = scrA;                   // alias: f0 (512*12=6144) dead after layer-0 reads
    float* w_s  = scrB + 128 * SCSTR;     // 2304
    float* b_s  = w_s + 2304;             // 96
    float* csi  = b_s + 96;               // 96
    float* csj  = csi + 96;               // 192

    const int tid = threadIdx.x;
    const int jb = blockIdx.x, ib = blockIdx.y;
    const int i0 = ib * TI, j0 = jb * TJ;

    // cooperative loads: weights, biases
    for (int v = tid; v < 256; v += PAIR_THREADS)  w_s[v]        = tp_w0[v];
    for (int v = tid; v < 1024; v += PAIR_THREADS) w_s[256 + v]  = tp_w[v];
    for (int v = tid; v < 1024; v += PAIR_THREADS) w_s[1280 + v] = tp_w[1024 + v];
    if (tid < 32) b_s[tid]      = tp_b0[tid];
    if (tid < 64) b_s[32 + tid] = tp_b[tid];

    // in-block sincos
    const float wfreq = 6.28318530717958647692f / 10.0f;   // 2*pi/L
    if (tid < 48) {
        int p = tid / 3, d = tid - 3 * p;
        float s, c;
        sincosf(x[(i0 + p) * 3 + d] * wfreq, &s, &c);
        csi[p * 6 + d] = c;
        csi[p * 6 + 3 + d] = s;
    } else if (tid >= 64 && tid < 160) {
        int q = tid - 64;
        int p = q / 3, d = q - 3 * p;
        float s, c;
        sincosf(x[(j0 + p) * 3 + d] * wfreq, &s, &c);
        csj[p * 6 + d] = c;
        csj[p * 6 + 3 + d] = s;
    }
    __syncthreads();

    // build tp0 features: [c0,c1,c2,s0,s1,s2,|s|,|c|]
    {
        int p = tid;
        int il = p >> 5, jl = p & 31;
        int gi = i0 + il, gj = j0 + jl;
        float s2 = 0.f, c2 = 0.f;
        #pragma unroll
        for (int d = 0; d < 3; d++) {
            float ci = csi[il * 6 + d], si = csi[il * 6 + 3 + d];
            float cj = csj[jl * 6 + d], sj = csj[jl * 6 + 3 + d];
            float cc = fmaf(ci, cj, si * sj);       // cos(a-b)
            float ss = fmaf(si, cj, -ci * sj);      // sin(a-b)
            c2 = fmaf(cc, cc, c2);
            s2 = fmaf(ss, ss, s2);
            f0_s[p * F0STR + d]     = cc;
            f0_s[p * F0STR + 3 + d] = ss;
        }
        bool diag = (gi == gj);
        f0_s[p * F0STR + 6] = diag ? 0.f : sqrtf(s2);
        f0_s[p * F0STR + 7] = diag ? 0.f : sqrtf(c2);
    }
    __syncthreads();

    // tp0 partial sums (8 features, offset 96)
    if (tid < 128) {
        int il = tid >> 3, k = tid & 7;
        const float* b = f0_s + (il * 32) * F0STR + k;
        float s0 = 0.f, s1 = 0.f, s2 = 0.f, s3 = 0.f;
        #pragma unroll
        for (int jl = 0; jl < 32; jl += 4) {
            s0 += b[(jl + 0) * F0STR]; s1 += b[(jl + 1) * F0STR];
            s2 += b[(jl + 2) * F0STR]; s3 += b[(jl + 3) * F0STR];
        }
        g_rowPart[((size_t)jb * NN + (i0 + il)) * FTOT + 96 + k] = (s0 + s1) + (s2 + s3);
    }
    if (tid < 256) {
        int jl = tid >> 3, k = tid & 7;
        const float* b = f0_s + jl * F0STR + k;
        float s0 = 0.f, s1 = 0.f, s2 = 0.f, s3 = 0.f;
        #pragma unroll
        for (int il2 = 0; il2 < 16; il2 += 4) {
            s0 += b[(il2 + 0) * 32 * F0STR]; s1 += b[(il2 + 1) * 32 * F0STR];
            s2 += b[(il2 + 2) * 32 * F0STR]; s3 += b[(il2 + 3) * 32 * F0STR];
        }
        g_colPart[((size_t)ib * NN + (j0 + jl)) * FTOT + 96 + k] = (s0 + s1) + (s2 + s3);
    }

    const int tr = tid >> 2, tc = tid & 3;
    const SPK spk = make_spk();
    u64 tp[4][4];       // this thread's current tile slice (register-resident residual)
    u64 colp[4];
    u64 acc[4][4];

    // ---- layer 0: tp1 = softplus(tp0 @ W0 + b0) ----
    gemm_tile2<2, F0STR>(f0_s, w_s, b_s, tr, tc, acc);
    #pragma unroll
    for (int m = 0; m < 4; m++)
        #pragma unroll
        for (int q = 0; q < 4; q++) tp[m][q] = softplus2p(acc[m][q], spk);
    #pragma unroll
    for (int q = 0; q < 4; q++)
        colp[q] = add2_(add2_(tp[0][q], tp[1][q]), add2_(tp[2][q], tp[3][q]));
    __syncthreads();                       // all f0 reads (tp0 sums + gemm0) done
    storeTile(tpA, scrA, tp, colp, tr, tc);  // scrA overwrites f0 (dead)
    __syncthreads();

    // ---- layers 1,2: tp += softplus(tp @ Wl + bl), ping-pong buffers ----
    #pragma unroll
    for (int L = 0; L < 2; L++) {
        float* bufR = L ? tpB : tpA;
        float* scrR = L ? scrB : scrA;
        float* bufW = L ? tpA : tpB;
        float* scrW = L ? scrA : scrB;

        // sums of the layer just stored (overlap their LDS latency with the gemm)
        rowSums(bufR, L * 32, i0, jb, tid);
        colStage2(scrR, L * 32, j0, ib, tid);

        gemm_tile2<8, TPSTR>(bufR, w_s + 256 + L * 1024, b_s + 32 + L * 32, tr, tc, acc);
        #pragma unroll
        for (int m = 0; m < 4; m++)
            #pragma unroll
            for (int q = 0; q < 4; q++)
                tp[m][q] = add2_(tp[m][q], softplus2p(acc[m][q], spk));   // residual from regs
        #pragma unroll
        for (int q = 0; q < 4; q++)
            colp[q] = add2_(add2_(tp[0][q], tp[1][q]), add2_(tp[2][q], tp[3][q]));

        storeTile(bufW, scrW, tp, colp, tr, tc);   // other buffer: no pre-store barrier
        __syncthreads();
    }

    // ---- tp3 sums (last store went to tpA/scrA) ----
    rowSums(tpA, 64, i0, jb, tid);
    colStage2(scrA, 64, j0, ib, tid);
}

// ---------------- dedicated high-occupancy partial reduction ----------------
// float4 per thread; rows: 32 slices, cols: 64 slices. Fixed order -> deterministic.
#define RT4 (NN * FTOT / 4)     // 26624 float4 outputs each for row/col
__global__ void __launch_bounds__(256)
reduceKernel() {
    int g = blockIdx.x * blockDim.x + threadIdx.x;
    const float4* rp = (const float4*)g_rowPart;
    const float4* cp = (const float4*)g_colPart;
    if (g < RT4) {
        float4 s = make_float4(0.f, 0.f, 0.f, 0.f);
        #pragma unroll 8
        for (int jb = 0; jb < NJB; jb++) {
            float4 v = rp[(size_t)jb * RT4 + g];
            s.x += v.x; s.y += v.y; s.z += v.z; s.w += v.w;
        }
        ((float4*)g_rowSum)[g] = s;
    } else if (g < 2 * RT4) {
        int h = g - RT4;
        float4 s = make_float4(0.f, 0.f, 0.f, 0.f);
        #pragma unroll 8
        for (int ib = 0; ib < NIB; ib++) {
            float4 v = cp[(size_t)ib * RT4 + h];
            s.x += v.x; s.y += v.y; s.z += v.z; s.w += v.w;
        }
        ((float4*)g_colSum)[h] = s;
    }
}

// ---------------- grid-wide barrier (deterministic; TB blocks co-resident) ----------------
__device__ __forceinline__ void gridBarrier() {
    __threadfence();
    __syncthreads();
    if (threadIdx.x == 0) {
        unsigned gen = *(volatile unsigned*)&g_barGen;
        if (atomicAdd(&g_barCount, 1) == TB - 1) {
            g_barCount = 0;
            __threadfence();
            atomicAdd(&g_barGen, 1);
        } else {
            while (*(volatile unsigned*)&g_barGen == gen) { __nanosleep(40); }
        }
        __threadfence();
    }
    __syncthreads();
}

// ---------------- fused tail kernel ----------------
// Phases: [level0 + mean partials] B [layer1] B [layer2] B [layer3 + final]
__global__ void __launch_bounds__(TT, 1)
tailKernel(const float* __restrict__ x,
           const float* __restrict__ sp_w0, const float* __restrict__ sp_b0,
           const float* __restrict__ sp_w,  const float* __restrict__ sp_b,
           const float* __restrict__ fin_w, const float* __restrict__ fin_b,
           float* __restrict__ out) {
    extern __shared__ float smem_f[];
    float* Ws   = smem_f;                 // 16384
    float* fs   = Ws + 16384;             // 8*260 = 2080
    float* sp_s = fs + 2080;              // 8*66  = 528
    float* mUp  = sp_s + 528;             // 64
    float* mDn  = mUp + 64;               // 64
    u64*   psum = (u64*)(mDn + 64);       // 2048 u64

    const int tid = threadIdx.x;
    const int bid = blockIdx.x;
    const float inv = 1.f / 1024.f;

    const int rl = tid >> 5, lane = tid & 31;
    const int r = bid * RPB + rl;
    const int o = lane * 2;

    // ---- phase 1: sp level 0 (sp==0 -> only tp0 means contribute) ----
    {
        float z0 = sp_b0[o], z1 = sp_b0[o + 1];
        #pragma unroll
        for (int k = 0; k < 8; k++) {
            float rm = g_rowSum[r * FTOT + 96 + k] * inv;
            float cm = g_colSum[r * FTOT + 96 + k] * inv;
            z0 = fmaf(rm, sp_w0[(9 + k) * 64 + o], z0);
            z1 = fmaf(rm, sp_w0[(9 + k) * 64 + o + 1], z1);
            z0 = fmaf(cm, sp_w0[(17 + k) * 64 + o], z0);
            z1 = fmaf(cm, sp_w0[(17 + k) * 64 + o + 1], z1);
        }
        sp_s[rl * 66 + o]     = softplus_exact(z0);
        sp_s[rl * 66 + o + 1] = softplus_exact(z1);
        __syncthreads();
        if (tid < 64) {
            float t = 0.f;
            #pragma unroll
            for (int rr = 0; rr < RPB; rr++) t += sp_s[rr * 66 + tid];
            g_meanPart[0][bid * 64 + tid] = t;
        }
    }
    gridBarrier();

    // ---- phases 2..4: sp += softplus(f @ W + b) ----
    const int ks = tid >> 5;    // split-K slice for the gemm
    #pragma unroll 1
    for (int it = 0; it < 3; it++) {
        const int rb = (it == 1) ? 1 : 0;                // read buffer
        const int wb = (it == 0) ? 1 : 0;                // write buffer (it==2: none)
        const int tpOff = it * 32;
        const float* W = sp_w + (size_t)it * 256 * 64;
        const float* bias = sp_b + it * 64;

        // mean finalize (fixed order, L2 reads)
        if (tid < 128) {
            int c = tid & 63, half = tid >> 6;
            float s = 0.f;
            #pragma unroll 8
            for (int b = 0; b < 64; b++) s += __ldcg(&g_meanPart[rb][(half * 64 + b) * 64 + c]);
            (half ? mDn : mUp)[c] = s * (1.f / 512.f);
        }
        // W -> smem
        for (int v = tid; v < 4096; v += TT)
            ((float4*)Ws)[v] = ((const float4*)W)[v];
        __syncthreads();

        // build f rows: [sp(64), up(64), dn(64), rowM(32), colM(32)]
        #pragma unroll
        for (int q = 0; q < 8; q++) {
            int idx = lane + 32 * q;
            float v;
            if (idx < 64)       v = sp_s[rl * 66 + idx];
            else if (idx < 128) v = mUp[idx - 64];
            else if (idx < 192) v = mDn[idx - 128];
            else if (idx < 224) v = g_rowSum[r * FTOT + tpOff + (idx - 192)] * inv;
            else                v = g_colSum[r * FTOT + tpOff + (idx - 224)] * inv;
            fs[rl * 260 + idx] = v;
        }
        __syncthreads();

        // split-K gemm: thread (ks, lane) covers k-slice ks*32..+31, col pair lane, all 8 rows
        u64 acc[RPB];
        #pragma unroll
        for (int rr = 0; rr < RPB; rr++) acc[rr] = 0ull;
        #pragma unroll 8
        for (int kk = 0; kk < 32; kk++) {
            int k = ks * 32 + kk;
            u64 w2 = *(const u64*)(Ws + k * 64 + lane * 2);
            #pragma unroll
            for (int rr = 0; rr < RPB; rr++) {
                float fk = fs[rr * 260 + k];
                acc[rr] = fma2_(dup2(fk), w2, acc[rr]);
            }
        }
        #pragma unroll
        for (int rr = 0; rr < RPB; rr++) psum[(ks * RPB + rr) * 32 + lane] = acc[rr];
        __syncthreads();

        // reduce split-K (fixed order) + bias + softplus + residual
        u64 s = psum[(0 * RPB + rl) * 32 + lane];
        #pragma unroll
        for (int ss = 1; ss < 8; ss++) s = add2_(s, psum[(ss * RPB + rl) * 32 + lane]);
        float z0, z1; up2(s, z0, z1);
        z0 += bias[o]; z1 += bias[o + 1];
        float n0 = sp_s[rl * 66 + o]     + softplus_exact(z0);
        float n1 = sp_s[rl * 66 + o + 1] + softplus_exact(z1);
        sp_s[rl * 66 + o]     = n0;
        sp_s[rl * 66 + o + 1] = n1;
        __syncthreads();

        if (it < 2) {
            if (tid < 64) {
                float t = 0.f;
                #pragma unroll
                for (int rr = 0; rr < RPB; rr++) t += sp_s[rr * 66 + tid];
                g_meanPart[wb][bid * 64 + tid] = t;
            }
            gridBarrier();
        } else {
            // ---- final: out = x + sp @ fin_w + fin_b (warp = one row) ----
            float p0 = n0 * fin_w[o * 3 + 0] + n1 * fin_w[(o + 1) * 3 + 0];
            float p1 = n0 * fin_w[o * 3 + 1] + n1 * fin_w[(o + 1) * 3 + 1];
            float p2 = n0 * fin_w[o * 3 + 2] + n1 * fin_w[(o + 1) * 3 + 2];
            #pragma unroll
            for (int off = 16; off > 0; off >>= 1) {
                p0 += __shfl_xor_sync(0xffffffff, p0, off);
                p1 += __shfl_xor_sync(0xffffffff, p1, off);
                p2 += __shfl_xor_sync(0xffffffff, p2, off);
            }
            if (lane == 0) {
                out[r * 3 + 0] = x[r * 3 + 0] + fin_b[0] + p0;
                out[r * 3 + 1] = x[r * 3 + 1] + fin_b[1] + p1;
                out[r * 3 + 2] = x[r * 3 + 2] + fin_b[2] + p2;
            }
        }
    }
}

// ---------------- launch ----------------
extern "C" void kernel_launch(void* const* d_in, const int* in_sizes, int n_in,
                              void* d_out, int out_size) {
    const float* x      = (const float*)d_in[0];
    const float* sp_w0  = (const float*)d_in[1];
    const float* sp_b0  = (const float*)d_in[2];
    const float* sp_w   = (const float*)d_in[3];
    const float* sp_b   = (const float*)d_in[4];
    const float* tp_w0  = (const float*)d_in[5];
    const float* tp_b0  = (const float*)d_in[6];
    const float* tp_w   = (const float*)d_in[7];
    const float* tp_b   = (const float*)d_in[8];
    const float* fin_w  = (const float*)d_in[9];
    const float* fin_b  = (const float*)d_in[10];
    float* out = (float*)d_out;

    const int PAIR_SMEM = (2 * 512 * TPSTR + 2 * 128 * SCSTR + 2304 + 96 + 96 + 192) * 4;  // 195072 B
    const int TAIL_SMEM = (16384 + 2080 + 528 + 64 + 64) * 4 + 2048 * 8;                   // 92864 B
    cudaFuncSetAttribute(pairKernel, cudaFuncAttributeMaxDynamicSharedMemorySize, PAIR_SMEM);
    cudaFuncSetAttribute(tailKernel, cudaFuncAttributeMaxDynamicSharedMemorySize, TAIL_SMEM);

    pairKernel<<<dim3(NJB, NIB), PAIR_THREADS, PAIR_SMEM>>>(x, tp_w0, tp_b0, tp_w, tp_b);
    reduceKernel<<<(2 * RT4 + 255) / 256, 256>>>();
    tailKernel<<<TB, TT, TAIL_SMEM>>>(x, sp_w0, sp_b0, sp_w, sp_b, fin_w, fin_b, out);
}

// round 13
// speedup vs baseline: 1.0315x; 1.0315x over previous
#include <cuda_runtime.h>
#include <math.h>

// Problem constants
#define NN 1024
#define TI 16
#define TJ 32
#define NIB (NN/TI)          // 64 i-blocks
#define NJB (NN/TJ)          // 32 j-blocks
#define NTILE (NJB*NIB)      // 2048 tiles
#define TPC 14               // tiles per persistent CTA
#define PAIR_BLOCKS ((NTILE + TPC - 1) / TPC)   // 147 (<=148 SMs, one wave)
#define FTOT 104             // per-particle reduced features: tp1(32) tp2(32) tp3(32) tp0(8)
#define TPSTR 36             // smem row stride for tp tile (floats), 16B-aligned rows
#define F0STR 12             // smem row stride for tp0 features
#define SCSTR 36             // scratch row stride (col partials), 16B-aligned
#define SPD 64
#define PAIR_THREADS 512

// tail kernel config
#define TB 128               // tail blocks (<=148 SMs -> co-resident, safe grid barrier)
#define TT 256               // tail threads
#define RPB 8                // rows per tail block

typedef unsigned long long u64;

// ---------------- device scratch (static allocation only) ----------------
__device__ float g_rowPart[(size_t)NJB * NN * FTOT];             // 13.6 MB
__device__ float g_colPart[(size_t)NIB * NN * FTOT];             // 27.3 MB
__device__ float g_rowSum[NN * FTOT];
__device__ float g_colSum[NN * FTOT];
__device__ float g_meanPart[2][TB * SPD];                        // double-buffered spin-mean partials
__device__ unsigned g_barCount;
__device__ unsigned g_barGen;

// ---------------- packed fp32x2 helpers ----------------
__device__ __forceinline__ u64 dup2(float v) {
    u64 r; asm("mov.b64 %0, {%1,%1};" : "=l"(r) : "f"(v)); return r;
}
__device__ __forceinline__ u64 pk2(float lo, float hi) {
    u64 r; asm("mov.b64 %0, {%1,%2};" : "=l"(r) : "f"(lo), "f"(hi)); return r;
}
__device__ __forceinline__ void up2(u64 p, float& lo, float& hi) {
    asm("mov.b64 {%0,%1}, %2;" : "=f"(lo), "=f"(hi) : "l"(p));
}
__device__ __forceinline__ u64 fma2_(u64 a, u64 b, u64 c) {
    u64 d; asm("fma.rn.f32x2 %0, %1, %2, %3;" : "=l"(d) : "l"(a), "l"(b), "l"(c)); return d;
}
__device__ __forceinline__ u64 mul2_(u64 a, u64 b) {
    u64 d; asm("mul.rn.f32x2 %0, %1, %2;" : "=l"(d) : "l"(a), "l"(b)); return d;
}
__device__ __forceinline__ u64 add2_(u64 a, u64 b) {
    u64 d; asm("add.rn.f32x2 %0, %1, %2;" : "=l"(d) : "l"(a), "l"(b)); return d;
}

// ---------------- softplus ----------------
__device__ __forceinline__ float softplus_exact(float x) {
    return fmaxf(x, 0.f) + log1pf(expf(-fabsf(x)));
}

struct SPK { u64 a, b, c, d, e, h; };  // packed poly coefficients
__device__ __forceinline__ SPK make_spk() {
    SPK k;
    k.a = dup2(-2.635168e-5f);
    k.b = dup2(3.4722222e-4f);
    k.c = dup2(-5.2083335e-3f);
    k.d = dup2(0.125f);
    k.e = dup2(0.69314718056f);
    k.h = dup2(0.5f);
    return k;
}
// softplus(x) = x/2 + ln(2 cosh(x/2)); even part poly in x^2 (|x|<=1: err < 2e-6)
__device__ __forceinline__ u64 softplus2p(u64 x2, const SPK& k) {
    u64 u = mul2_(x2, x2);
    u64 h = fma2_(u, k.a, k.b);
    h = fma2_(u, h, k.c);
    h = fma2_(u, h, k.d);
    h = fma2_(u, h, k.e);
    u64 r = fma2_(x2, k.h, h);
    float xl, xh; up2(x2, xl, xh);
    if (fabsf(xl) > 1.0f || fabsf(xh) > 1.0f) {
        float rl = fmaxf(xl, 0.f) + log1pf(__expf(-fabsf(xl)));
        float rh = fmaxf(xh, 0.f) + log1pf(__expf(-fabsf(xh)));
        r = pk2(rl, rh);
    }
    return r;
}

// ---------------- pair kernel: persistent, fused tp stream ----------------
// tile: TI=16 i x TJ=32 j = 512 pairs, 512 threads
// GEMM thread (tr,tc): pairs {tr, tr+128, tr+256, tr+384}, packed cols tc*8..tc*8+7
template<int K4, int AS>
__device__ __forceinline__ void gemm_tile2(const float* __restrict__ A,
                                           const float* __restrict__ W,
                                           const float* __restrict__ bias,
                                           int tr, int tc, u64 acc[4][4]) {
    const ulonglong2* bp = (const ulonglong2*)(bias + tc * 8);
    ulonglong2 bb0 = bp[0], bb1 = bp[1];
    #pragma unroll
    for (int m = 0; m < 4; m++) {
        acc[m][0] = bb0.x; acc[m][1] = bb0.y; acc[m][2] = bb1.x; acc[m][3] = bb1.y;
    }
    #pragma unroll
    for (int k4 = 0; k4 < K4; k4++) {
        float4 a[4];
        #pragma unroll
        for (int m = 0; m < 4; m++)
            a[m] = *(const float4*)(A + (tr + 128 * m) * AS + k4 * 4);
        #pragma unroll
        for (int kk = 0; kk < 4; kk++) {
            const ulonglong2* wr = (const ulonglong2*)(W + (k4 * 4 + kk) * 32 + tc * 8);
            ulonglong2 w0 = wr[0], w1 = wr[1];
            #pragma unroll
            for (int m = 0; m < 4; m++) {
                float av = (&a[m].x)[kk];
                u64 av2 = dup2(av);
                acc[m][0] = fma2_(av2, w0.x, acc[m][0]);
                acc[m][1] = fma2_(av2, w0.y, acc[m][1]);
                acc[m][2] = fma2_(av2, w1.x, acc[m][2]);
                acc[m][3] = fma2_(av2, w1.y, acc[m][3]);
            }
        }
    }
}

// row sums from tile (4-way ILP): 512 threads -> 16 rows x 32 feats
__device__ __forceinline__ void rowSums(const float* __restrict__ tp_s, int off,
                                        int i0, int jb, int tid) {
    int il = tid >> 5, n = tid & 31;
    const float* b = tp_s + (il * 32) * TPSTR + n;
    float s0 = 0.f, s1 = 0.f, s2 = 0.f, s3 = 0.f;
    #pragma unroll
    for (int jl = 0; jl < 32; jl += 4) {
        s0 += b[(jl + 0) * TPSTR];
        s1 += b[(jl + 1) * TPSTR];
        s2 += b[(jl + 2) * TPSTR];
        s3 += b[(jl + 3) * TPSTR];
    }
    g_rowPart[((size_t)jb * NN + (i0 + il)) * FTOT + off + n] = (s0 + s1) + (s2 + s3);
}

// col sums stage 2: combine 4 register-presummed partials per (jl, n)
__device__ __forceinline__ void colStage2(const float* __restrict__ scratch, int off,
                                          int j0, int ib, int tid) {
    #pragma unroll
    for (int rep = 0; rep < 2; rep++) {
        int v = tid + rep * 512;
        int jl = v >> 5, n = v & 31;
        float s = (scratch[jl * SCSTR + n] + scratch[(jl + 32) * SCSTR + n])
                + (scratch[(jl + 64) * SCSTR + n] + scratch[(jl + 96) * SCSTR + n]);
        g_colPart[((size_t)ib * NN + (j0 + jl)) * FTOT + off + n] = s;
    }
}

// store thread's tile slice + col partials to the write buffer
__device__ __forceinline__ void storeTile(float* __restrict__ bufW, float* __restrict__ scrW,
                                          const u64 tp[4][4], const u64 colp[4],
                                          int tr, int tc) {
    #pragma unroll
    for (int m = 0; m < 4; m++) {
        ulonglong2* row = (ulonglong2*)(bufW + (tr + 128 * m) * TPSTR + tc * 8);
        row[0] = make_ulonglong2(tp[m][0], tp[m][1]);
        row[1] = make_ulonglong2(tp[m][2], tp[m][3]);
    }
    ulonglong2* sc = (ulonglong2*)(scrW + tr * SCSTR + tc * 8);
    sc[0] = make_ulonglong2(colp[0], colp[1]);
    sc[1] = make_ulonglong2(colp[2], colp[3]);
}

__global__ void __launch_bounds__(PAIR_THREADS, 1)
pairKernel(const float* __restrict__ x,
           const float* __restrict__ tp_w0, const float* __restrict__ tp_b0,
           const float* __restrict__ tp_w,  const float* __restrict__ tp_b) {
    extern __shared__ float smem_f[];
    float* tpA  = smem_f;                 // 512*36 = 18432 floats
    float* tpB  = tpA + 512 * TPSTR;      // 18432 floats
    float* scrA = tpB + 512 * TPSTR;      // 128*36 = 4608 floats
    float* scrB = scrA + 128 * SCSTR;     // 4608 floats
    float* f0_s = scrA;                   // alias: f0 (512*12=6144) dead after layer-0 reads
    float* w_s  = scrB + 128 * SCSTR;     // 2304
    float* b_s  = w_s + 2304;             // 96
    float* csi  = b_s + 96;               // 96
    float* csj  = csi + 96;               // 192

    const int tid = threadIdx.x;

    // ---- one-time prologue: weights + biases ----
    for (int v = tid; v < 256; v += PAIR_THREADS)  w_s[v]        = tp_w0[v];
    for (int v = tid; v < 1024; v += PAIR_THREADS) w_s[256 + v]  = tp_w[v];
    for (int v = tid; v < 1024; v += PAIR_THREADS) w_s[1280 + v] = tp_w[1024 + v];
    if (tid < 32) b_s[tid]      = tp_b0[tid];
    if (tid < 64) b_s[32 + tid] = tp_b[tid];

    const float wfreq = 6.28318530717958647692f / 10.0f;   // 2*pi/L
    const int tr = tid >> 2, tc = tid & 3;
    const SPK spk = make_spk();
    int prevIb = -1;

    const int t0 = blockIdx.x * TPC;
    const int t1 = (t0 + TPC < NTILE) ? t0 + TPC : NTILE;

    for (int t = t0; t < t1; t++) {
        const int jb = t & (NJB - 1), ib = t >> 5;
        const int i0 = ib * TI, j0 = jb * TJ;

        // per-tile sincos: csj always (warps 0-2), csi on ib change (warps 6-7)
        if (tid < 96) {
            int p = tid / 3, d = tid - 3 * (tid / 3);
            float s, c;
            sincosf(x[(j0 + p) * 3 + d] * wfreq, &s, &c);
            csj[p * 6 + d] = c;
            csj[p * 6 + 3 + d] = s;
        } else if (ib != prevIb && tid >= 192 && tid < 240) {
            int q = tid - 192;
            int p = q / 3, d = q - 3 * p;
            float s, c;
            sincosf(x[(i0 + p) * 3 + d] * wfreq, &s, &c);
            csi[p * 6 + d] = c;
            csi[p * 6 + 3 + d] = s;
        }
        prevIb = ib;
        __syncthreads();   // also protects prev tile's scratch/tile reads from f0 overwrite

        // build tp0 features: [c0,c1,c2,s0,s1,s2,|s|,|c|]
        {
            int p = tid;
            int il = p >> 5, jl = p & 31;
            int gi = i0 + il, gj = j0 + jl;
            float s2 = 0.f, c2 = 0.f;
            #pragma unroll
            for (int d = 0; d < 3; d++) {
                float ci = csi[il * 6 + d], si = csi[il * 6 + 3 + d];
                float cj = csj[jl * 6 + d], sj = csj[jl * 6 + 3 + d];
                float cc = fmaf(ci, cj, si * sj);       // cos(a-b)
                float ss = fmaf(si, cj, -ci * sj);      // sin(a-b)
                c2 = fmaf(cc, cc, c2);
                s2 = fmaf(ss, ss, s2);
                f0_s[p * F0STR + d]     = cc;
                f0_s[p * F0STR + 3 + d] = ss;
            }
            bool diag = (gi == gj);
            f0_s[p * F0STR + 6] = diag ? 0.f : sqrtf(s2);
            f0_s[p * F0STR + 7] = diag ? 0.f : sqrtf(c2);
        }
        __syncthreads();

        // tp0 partial sums (8 features, offset 96)
        if (tid < 128) {
            int il = tid >> 3, k = tid & 7;
            const float* b = f0_s + (il * 32) * F0STR + k;
            float s0 = 0.f, s1 = 0.f, s2 = 0.f, s3 = 0.f;
            #pragma unroll
            for (int jl = 0; jl < 32; jl += 4) {
                s0 += b[(jl + 0) * F0STR]; s1 += b[(jl + 1) * F0STR];
                s2 += b[(jl + 2) * F0STR]; s3 += b[(jl + 3) * F0STR];
            }
            g_rowPart[((size_t)jb * NN + (i0 + il)) * FTOT + 96 + k] = (s0 + s1) + (s2 + s3);
        }
        if (tid < 256) {
            int jl = tid >> 3, k = tid & 7;
            const float* b = f0_s + jl * F0STR + k;
            float s0 = 0.f, s1 = 0.f, s2 = 0.f, s3 = 0.f;
            #pragma unroll
            for (int il2 = 0; il2 < 16; il2 += 4) {
                s0 += b[(il2 + 0) * 32 * F0STR]; s1 += b[(il2 + 1) * 32 * F0STR];
                s2 += b[(il2 + 2) * 32 * F0STR]; s3 += b[(il2 + 3) * 32 * F0STR];
            }
            g_colPart[((size_t)ib * NN + (j0 + jl)) * FTOT + 96 + k] = (s0 + s1) + (s2 + s3);
        }

        u64 tp[4][4];       // register-resident tile slice (residual source)
        u64 colp[4];
        u64 acc[4][4];

        // ---- layer 0: tp1 = softplus(tp0 @ W0 + b0) ----
        gemm_tile2<2, F0STR>(f0_s, w_s, b_s, tr, tc, acc);
        #pragma unroll
        for (int m = 0; m < 4; m++)
            #pragma unroll
            for (int q = 0; q < 4; q++) tp[m][q] = softplus2p(acc[m][q], spk);
        #pragma unroll
        for (int q = 0; q < 4; q++)
            colp[q] = add2_(add2_(tp[0][q], tp[1][q]), add2_(tp[2][q], tp[3][q]));
        __syncthreads();                       // all f0 reads (tp0 sums + gemm0) done
        storeTile(tpA, scrA, tp, colp, tr, tc);  // scrA overwrites f0 (dead)
        __syncthreads();

        // ---- layers 1,2: tp += softplus(tp @ Wl + bl), ping-pong buffers ----
        #pragma unroll
        for (int L = 0; L < 2; L++) {
            float* bufR = L ? tpB : tpA;
            float* scrR = L ? scrB : scrA;
            float* bufW = L ? tpA : tpB;
            float* scrW = L ? scrA : scrB;

            // sums of the layer just stored (overlap their LDS latency with the gemm)
            rowSums(bufR, L * 32, i0, jb, tid);
            colStage2(scrR, L * 32, j0, ib, tid);

            gemm_tile2<8, TPSTR>(bufR, w_s + 256 + L * 1024, b_s + 32 + L * 32, tr, tc, acc);
            #pragma unroll
            for (int m = 0; m < 4; m++)
                #pragma unroll
                for (int q = 0; q < 4; q++)
                    tp[m][q] = add2_(tp[m][q], softplus2p(acc[m][q], spk));   // residual from regs
            #pragma unroll
            for (int q = 0; q < 4; q++)
                colp[q] = add2_(add2_(tp[0][q], tp[1][q]), add2_(tp[2][q], tp[3][q]));

            storeTile(bufW, scrW, tp, colp, tr, tc);   // other buffer: no pre-store barrier
            __syncthreads();
        }

        // ---- tp3 sums (last store went to tpA/scrA); loop-top barrier protects them ----
        rowSums(tpA, 64, i0, jb, tid);
        colStage2(scrA, 64, j0, ib, tid);
    }
}

// ---------------- dedicated high-occupancy partial reduction ----------------
// float4 per thread; rows: 32 slices, cols: 64 slices. Fixed order -> deterministic.
#define RT4 (NN * FTOT / 4)     // 26624 float4 outputs each for row/col
__global__ void __launch_bounds__(256)
reduceKernel() {
    int g = blockIdx.x * blockDim.x + threadIdx.x;
    const float4* rp = (const float4*)g_rowPart;
    const float4* cp = (const float4*)g_colPart;
    if (g < RT4) {
        float4 s = make_float4(0.f, 0.f, 0.f, 0.f);
        #pragma unroll 8
        for (int jb = 0; jb < NJB; jb++) {
            float4 v = rp[(size_t)jb * RT4 + g];
            s.x += v.x; s.y += v.y; s.z += v.z; s.w += v.w;
        }
        ((float4*)g_rowSum)[g] = s;
    } else if (g < 2 * RT4) {
        int h = g - RT4;
        float4 s = make_float4(0.f, 0.f, 0.f, 0.f);
        #pragma unroll 8
        for (int ib = 0; ib < NIB; ib++) {
            float4 v = cp[(size_t)ib * RT4 + h];
            s.x += v.x; s.y += v.y; s.z += v.z; s.w += v.w;
        }
        ((float4*)g_colSum)[h] = s;
    }
}

// ---------------- grid-wide barrier (deterministic; TB blocks co-resident) ----------------
__device__ __forceinline__ void gridBarrier() {
    __threadfence();
    __syncthreads();
    if (threadIdx.x == 0) {
        unsigned gen = *(volatile unsigned*)&g_barGen;
        if (atomicAdd(&g_barCount, 1) == TB - 1) {
            g_barCount = 0;
            __threadfence();
            atomicAdd(&g_barGen, 1);
        } else {
            while (*(volatile unsigned*)&g_barGen == gen) { __nanosleep(40); }
        }
        __threadfence();
    }
    __syncthreads();
}

// ---------------- fused tail kernel ----------------
// Phases: [level0 + mean partials] B [layer1] B [layer2] B [layer3 + final]
__global__ void __launch_bounds__(TT, 1)
tailKernel(const float* __restrict__ x,
           const float* __restrict__ sp_w0, const float* __restrict__ sp_b0,
           const float* __restrict__ sp_w,  const float* __restrict__ sp_b,
           const float* __restrict__ fin_w, const float* __restrict__ fin_b,
           float* __restrict__ out) {
    extern __shared__ float smem_f[];
    float* Ws   = smem_f;                 // 16384
    float* fs   = Ws + 16384;             // 8*260 = 2080
    float* sp_s = fs + 2080;              // 8*66  = 528
    float* mUp  = sp_s + 528;             // 64
    float* mDn  = mUp + 64;               // 64
    u64*   psum = (u64*)(mDn + 64);       // 2048 u64

    const int tid = threadIdx.x;
    const int bid = blockIdx.x;
    const float inv = 1.f / 1024.f;

    const int rl = tid >> 5, lane = tid & 31;
    const int r = bid * RPB + rl;
    const int o = lane * 2;

    // ---- phase 1: sp level 0 (sp==0 -> only tp0 means contribute) ----
    {
        float z0 = sp_b0[o], z1 = sp_b0[o + 1];
        #pragma unroll
        for (int k = 0; k < 8; k++) {
            float rm = g_rowSum[r * FTOT + 96 + k] * inv;
            float cm = g_colSum[r * FTOT + 96 + k] * inv;
            z0 = fmaf(rm, sp_w0[(9 + k) * 64 + o], z0);
            z1 = fmaf(rm, sp_w0[(9 + k) * 64 + o + 1], z1);
            z0 = fmaf(cm, sp_w0[(17 + k) * 64 + o], z0);
            z1 = fmaf(cm, sp_w0[(17 + k) * 64 + o + 1], z1);
        }
        sp_s[rl * 66 + o]     = softplus_exact(z0);
        sp_s[rl * 66 + o + 1] = softplus_exact(z1);
        __syncthreads();
        if (tid < 64) {
            float t = 0.f;
            #pragma unroll
            for (int rr = 0; rr < RPB; rr++) t += sp_s[rr * 66 + tid];
            g_meanPart[0][bid * 64 + tid] = t;
        }
    }
    gridBarrier();

    // ---- phases 2..4: sp += softplus(f @ W + b) ----
    const int ks = tid >> 5;    // split-K slice for the gemm
    #pragma unroll 1
    for (int it = 0; it < 3; it++) {
        const int rb = (it == 1) ? 1 : 0;                // read buffer
        const int wb = (it == 0) ? 1 : 0;                // write buffer (it==2: none)
        const int tpOff = it * 32;
        const float* W = sp_w + (size_t)it * 256 * 64;
        const float* bias = sp_b + it * 64;

        // mean finalize (fixed order, L2 reads)
        if (tid < 128) {
            int c = tid & 63, half = tid >> 6;
            float s = 0.f;
            #pragma unroll 8
            for (int b = 0; b < 64; b++) s += __ldcg(&g_meanPart[rb][(half * 64 + b) * 64 + c]);
            (half ? mDn : mUp)[c] = s * (1.f / 512.f);
        }
        // W -> smem
        for (int v = tid; v < 4096; v += TT)
            ((float4*)Ws)[v] = ((const float4*)W)[v];
        __syncthreads();

        // build f rows: [sp(64), up(64), dn(64), rowM(32), colM(32)]
        #pragma unroll
        for (int q = 0; q < 8; q++) {
            int idx = lane + 32 * q;
            float v;
            if (idx < 64)       v = sp_s[rl * 66 + idx];
            else if (idx < 128) v = mUp[idx - 64];
            else if (idx < 192) v = mDn[idx - 128];
            else if (idx < 224) v = g_rowSum[r * FTOT + tpOff + (idx - 192)] * inv;
            else                v = g_colSum[r * FTOT + tpOff + (idx - 224)] * inv;
            fs[rl * 260 + idx] = v;
        }
        __syncthreads();

        // split-K gemm: thread (ks, lane) covers k-slice ks*32..+31, col pair lane, all 8 rows
        u64 acc[RPB];
        #pragma unroll
        for (int rr = 0; rr < RPB; rr++) acc[rr] = 0ull;
        #pragma unroll 8
        for (int kk = 0; kk < 32; kk++) {
            int k = ks * 32 + kk;
            u64 w2 = *(const u64*)(Ws + k * 64 + lane * 2);
            #pragma unroll
            for (int rr = 0; rr < RPB; rr++) {
                float fk = fs[rr * 260 + k];
                acc[rr] = fma2_(dup2(fk), w2, acc[rr]);
            }
        }
        #pragma unroll
        for (int rr = 0; rr < RPB; rr++) psum[(ks * RPB + rr) * 32 + lane] = acc[rr];
        __syncthreads();

        // reduce split-K (fixed order) + bias + softplus + residual
        u64 s = psum[(0 * RPB + rl) * 32 + lane];
        #pragma unroll
        for (int ss = 1; ss < 8; ss++) s = add2_(s, psum[(ss * RPB + rl) * 32 + lane]);
        float z0, z1; up2(s, z0, z1);
        z0 += bias[o]; z1 += bias[o + 1];
        float n0 = sp_s[rl * 66 + o]     + softplus_exact(z0);
        float n1 = sp_s[rl * 66 + o + 1] + softplus_exact(z1);
        sp_s[rl * 66 + o]     = n0;
        sp_s[rl * 66 + o + 1] = n1;
        __syncthreads();

        if (it < 2) {
            if (tid < 64) {
                float t = 0.f;
                #pragma unroll
                for (int rr = 0; rr < RPB; rr++) t += sp_s[rr * 66 + tid];
                g_meanPart[wb][bid * 64 + tid] = t;
            }
            gridBarrier();
        } else {
            // ---- final: out = x + sp @ fin_w + fin_b (warp = one row) ----
            float p0 = n0 * fin_w[o * 3 + 0] + n1 * fin_w[(o + 1) * 3 + 0];
            float p1 = n0 * fin_w[o * 3 + 1] + n1 * fin_w[(o + 1) * 3 + 1];
            float p2 = n0 * fin_w[o * 3 + 2] + n1 * fin_w[(o + 1) * 3 + 2];
            #pragma unroll
            for (int off = 16; off > 0; off >>= 1) {
                p0 += __shfl_xor_sync(0xffffffff, p0, off);
                p1 += __shfl_xor_sync(0xffffffff, p1, off);
                p2 += __shfl_xor_sync(0xffffffff, p2, off);
            }
            if (lane == 0) {
                out[r * 3 + 0] = x[r * 3 + 0] + fin_b[0] + p0;
                out[r * 3 + 1] = x[r * 3 + 1] + fin_b[1] + p1;
                out[r * 3 + 2] = x[r * 3 + 2] + fin_b[2] + p2;
            }
        }
    }
}

// ---------------- launch ----------------
extern "C" void kernel_launch(void* const* d_in, const int* in_sizes, int n_in,
                              void* d_out, int out_size) {
    const float* x      = (const float*)d_in[0];
    const float* sp_w0  = (const float*)d_in[1];
    const float* sp_b0  = (const float*)d_in[2];
    const float* sp_w   = (const float*)d_in[3];
    const float* sp_b   = (const float*)d_in[4];
    const float* tp_w0  = (const float*)d_in[5];
    const float* tp_b0  = (const float*)d_in[6];
    const float* tp_w   = (const float*)d_in[7];
    const float* tp_b   = (const float*)d_in[8];
    const float* fin_w  = (const float*)d_in[9];
    const float* fin_b  = (const float*)d_in[10];
    float* out = (float*)d_out;

    const int PAIR_SMEM = (2 * 512 * TPSTR + 2 * 128 * SCSTR + 2304 + 96 + 96 + 192) * 4;  // 195072 B
    const int TAIL_SMEM = (16384 + 2080 + 528 + 64 + 64) * 4 + 2048 * 8;                   // 92864 B
    cudaFuncSetAttribute(pairKernel, cudaFuncAttributeMaxDynamicSharedMemorySize, PAIR_SMEM);
    cudaFuncSetAttribute(tailKernel, cudaFuncAttributeMaxDynamicSharedMemorySize, TAIL_SMEM);

    pairKernel<<<PAIR_BLOCKS, PAIR_THREADS, PAIR_SMEM>>>(x, tp_w0, tp_b0, tp_w, tp_b);
    reduceKernel<<<(2 * RT4 + 255) / 256, 256>>>();
    tailKernel<<<TB, TT, TAIL_SMEM>>>(x, sp_w0, sp_b0, sp_w, sp_b, fin_w, fin_b, out);
}